// round 9
// baseline (speedup 1.0000x reference)
#include <cuda_runtime.h>
#include <math.h>

#define NK     10000
#define SEQ    512
#define XS_POS 1792                      // worst read = 1023 + pad + (M-1)d <= 1791 (guarded)
#define SMEM_BYTES (XS_POS * 8 * 4)      // 57344 B dynamic shared
#define NT     256
#define NBLK   592                       // 4 CTAs/SM * 148 SMs, all resident
#define TOTAL_WARPS (NBLK * (NT / 32))   // 4736

typedef unsigned long long ull;

__device__ int g_ctr;                    // work-steal cursor (self-resetting)
__device__ int g_done;                   // finished-warp count (self-resetting)

static __device__ __forceinline__ ull pack2(float a, float b) {
    ull r; asm("mov.b64 %0, {%1, %2};" : "=l"(r) : "f"(a), "f"(b)); return r;
}
static __device__ __forceinline__ ull fma2(ull a, ull b, ull c) {
    ull r; asm("fma.rn.f32x2 %0, %1, %2, %3;" : "=l"(r) : "l"(a), "l"(b), "l"(c)); return r;
}
static __device__ __forceinline__ unsigned lo32(ull v) { return (unsigned)v; }
static __device__ __forceinline__ unsigned hi32(ull v) { return (unsigned)(v >> 32); }

// Process rocket conv-kernel i with compile-time tap count K and tile height M.
// Lanes: c = lane>>1 (16 tile-lanes), h = lane&1 (batch half). Tile = M chain-
// consecutive outputs t0..t0+(M-1)d sharing K+M-1 loads. Accumulates s' = -s:
// max s = -min s'; ppv count = #(s' < 0) via packed sign bytes.
// SAFETY: caller guarantees pad + (M-1)*dil <= 768 so all reads < XS_POS.
template<int K, int M>
static __device__ __forceinline__ void process_i(
    const ulonglong2* __restrict__ xsu, int i, int c, int h,
    const float* __restrict__ w, float bias, int dil, int lo, int pad,
    float* __restrict__ out)
{
    ull wn[K];
#pragma unroll
    for (int j = 0; j < K; ++j) wn[j] = pack2(-w[j], -w[j]);
    const ull biasn = pack2(-bias, -bias);

    const int dM = dil * M;
    const float inv_d = 1.0f / (float)dil;
    const int inc = dil * 2;                           // ulonglong2-index step per tap
    const int base0 = (SEQ - pad) * 2 + h;

    // per-lane start (stripe, off) for tile-index j0 = c : one guarded float div
    int stripe = __float2int_rd(__int2float_rn(c) * inv_d);
    int off = c - stripe * dil;
    if (off < 0)         { --stripe; off += dil; }
    else if (off >= dil) { ++stripe; off -= dil; }
    // stride-16 decomposition: 16 = q16*dil + r16
    int q16 = __float2int_rd(16.0f * inv_d);
    int r16 = 16 - q16 * dil;
    if (r16 < 0)         { --q16; r16 += dil; }
    else if (r16 >= dil) { ++q16; r16 -= dil; }
    int t0 = stripe * dM + off;
    const int C0 = q16 * dM + r16;                     // t0 step per 16 tiles (no carry)
    const int D1 = dM - dil;                           // extra on off-carry

    int qd[M];
#pragma unroll
    for (int q = 0; q < M; ++q) qd[q] = q * dil;

    float mn0 = INFINITY, mn1 = INFINITY, mn2 = INFINITY, mn3 = INFINITY;
    unsigned c4 = 0u;                                  // 4x8-bit per-batch counts (<=64 each)

    for (;;) {
        if (t0 >= lo) break;                           // t0 monotone => exact exit

        int idx = base0 + t0 * 2;
        ull aL[M], aH[M];
#pragma unroll
        for (int q = 0; q < M; ++q) { aL[q] = biasn; aH[q] = biasn; }

#pragma unroll
        for (int v = 0; v < K + M - 1; ++v) {
            const int ph = idx ^ ((idx >> 3) & 6);     // bank swizzle within 128B row
            const ulonglong2 L = xsu[ph];
#pragma unroll
            for (int q = 0; q < M; ++q) {
                const int jj = v - q;
                if (jj >= 0 && jj < K) {
                    aL[q] = fma2(wn[jj], L.x, aL[q]);
                    aH[q] = fma2(wn[jj], L.y, aH[q]);
                }
            }
            idx += inc;
        }

        const int rem = lo - t0;                       // >= 1 here
#pragma unroll
        for (int q = 0; q < M; ++q) {
            if (q == 0 || qd[q] < rem) {
                const unsigned u0 = lo32(aL[q]), u1 = hi32(aL[q]);
                const unsigned u2 = lo32(aH[q]), u3 = hi32(aH[q]);
                mn0 = fminf(mn0, __uint_as_float(u0));
                mn1 = fminf(mn1, __uint_as_float(u1));
                mn2 = fminf(mn2, __uint_as_float(u2));
                mn3 = fminf(mn3, __uint_as_float(u3));
                unsigned t1 = __byte_perm(u0, u1, 0x0073);  // [b3(u0), b3(u1), x, x]
                unsigned t2 = __byte_perm(u2, u3, 0x7300);  // [x, x, b3(u2), b3(u3)]
                unsigned tm = __byte_perm(t1, t2, 0x7610);  // [s0, s1, s2, s3] sign bytes
                c4 += (tm >> 7) & 0x01010101u;
            }
        }

        // advance 16 tiles: off += r16 with single carry into t0
        off += r16;
        t0 += C0;
        if (off >= dil) { off -= dil; t0 += D1; }
    }

    // reduce across the 16 tile-lanes (xor offsets 2..16 keep h fixed);
    // counts unpacked to 2x16-bit (sums <= 1022, no carry)
    unsigned p01 = __byte_perm(c4, 0u, 0x4140);        // cnt0 | cnt1<<16
    unsigned p23 = __byte_perm(c4, 0u, 0x4342);        // cnt2 | cnt3<<16
#pragma unroll
    for (int offx = 2; offx < 32; offx <<= 1) {
        mn0 = fminf(mn0, __shfl_xor_sync(0xffffffffu, mn0, offx));
        mn1 = fminf(mn1, __shfl_xor_sync(0xffffffffu, mn1, offx));
        mn2 = fminf(mn2, __shfl_xor_sync(0xffffffffu, mn2, offx));
        mn3 = fminf(mn3, __shfl_xor_sync(0xffffffffu, mn3, offx));
        p01 += __shfl_xor_sync(0xffffffffu, p01, offx);
        p23 += __shfl_xor_sync(0xffffffffu, p23, offx);
    }

    if (c == 0) {
        const float il = 1.f / (float)lo;
        float2* o2 = reinterpret_cast<float2*>(out);
        o2[(4 * h + 0) * NK + i] = make_float2(-mn0, (float)(p01 & 0xFFFFu) * il);
        o2[(4 * h + 1) * NK + i] = make_float2(-mn1, (float)(p01 >> 16) * il);
        o2[(4 * h + 2) * NK + i] = make_float2(-mn2, (float)(p23 & 0xFFFFu) * il);
        o2[(4 * h + 3) * NK + i] = make_float2(-mn3, (float)(p23 >> 16) * il);
    }
}

__global__ __launch_bounds__(NT, 4)
void rocket_kernel(const float* __restrict__ x,     // (8,1,512)
                   const float* __restrict__ W,     // (10000,1,11)
                   const float* __restrict__ Bias,  // (10000,)
                   const int*   __restrict__ dil_,  // (10000,)
                   const int*   __restrict__ lo_,   // (10000,)
                   float*       __restrict__ out)   // (8, 20000) interleaved (max, ppv)
{
    extern __shared__ float xs[];   // swizzled [pos][8 batches], zero-padded
    const int tid = threadIdx.x;

    // Prologue (single barrier): zero only the two pad regions, transpose x into
    // the middle. Regions disjoint in idx4 space; pad ranges are 128B-row aligned
    // and the swizzle permutes only within rows, so physical zeroing is exact.
    float4* z4 = reinterpret_cast<float4*>(xs);
#pragma unroll
    for (int t = tid; t < 1024; t += NT)
        z4[t] = make_float4(0.f, 0.f, 0.f, 0.f);
#pragma unroll
    for (int t = tid; t < 1536; t += NT)
        z4[2048 + t] = make_float4(0.f, 0.f, 0.f, 0.f);
    for (int t = tid; t < 8 * SEQ; t += NT) {
        int b = t >> 9;
        int s = t & 511;
        int idx4 = (s + SEQ) * 2 + (b >> 2);
        int ph = idx4 ^ ((idx4 >> 3) & 6);
        xs[ph * 4 + (b & 3)] = x[t];
    }
    __syncthreads();

    const int lane = tid & 31;
    const int c = lane >> 1;
    const int h = lane & 1;
    const ulonglong2* xsu = reinterpret_cast<const ulonglong2*>(xs);

    int i;
    if (lane == 0) i = atomicAdd(&g_ctr, 1);
    i = __shfl_sync(0xffffffffu, i, 0);

    while (i < NK) {
        // pre-steal next item (ATOMG latency overlaps this item's compute) and
        // prefetch its param lines into L1.
        int inext;
        if (lane == 0) {
            inext = atomicAdd(&g_ctr, 1);
            if (inext < NK) {
                asm volatile("prefetch.global.L1 [%0];" :: "l"(W + inext * 11));
                asm volatile("prefetch.global.L1 [%0];" :: "l"(W + inext * 11 + 10));
                asm volatile("prefetch.global.L1 [%0];" :: "l"(Bias + inext));
                asm volatile("prefetch.global.L1 [%0];" :: "l"(dil_ + inext));
                asm volatile("prefetch.global.L1 [%0];" :: "l"(lo_ + inext));
            }
        }
        inext = __shfl_sync(0xffffffffu, inext, 0);

        float w[11];
        const float* wr = W + i * 11;
#pragma unroll
        for (int j = 0; j < 11; ++j) w[j] = __ldg(wr + j);
        const float bias = __ldg(Bias + i);
        const int   dil  = __ldg(dil_ + i);
        const int   lo   = __ldg(lo_ + i);

        // recover tap count from exact-zero weight tail
        if (w[7] == 0.f && w[8] == 0.f) {
            const int pad = (lo - SEQ + dil * 6) >> 1;
            if (pad + 5 * dil <= 768)   // M=6 tile stays inside XS_POS
                process_i<7, 6>(xsu, i, c, h, w, bias, dil, lo, pad, out);
            else
                process_i<7, 4>(xsu, i, c, h, w, bias, dil, lo, pad, out);
        } else if (w[9] == 0.f && w[10] == 0.f) {
            const int pad = (lo - SEQ + dil * 8) >> 1;   // pad+4d <= 759 always
            process_i<9, 5>(xsu, i, c, h, w, bias, dil, lo, pad, out);
        } else {
            const int pad = (lo - SEQ + dil * 10) >> 1;  // pad+3d <= 663 always
            process_i<11, 4>(xsu, i, c, h, w, bias, dil, lo, pad, out);
        }
        i = inext;
    }

    // Self-resetting counters: a warp increments g_done only after its final
    // g_ctr atomic, so the last arrival implies all steals are done. Kernel
    // completion fences the stores for the next graph replay.
    if (lane == 0) {
        int d = atomicAdd(&g_done, 1);
        if (d == TOTAL_WARPS - 1) {
            g_ctr = 0;
            g_done = 0;
        }
    }
}

extern "C" void kernel_launch(void* const* d_in, const int* in_sizes, int n_in,
                              void* d_out, int out_size) {
    const float* x    = (const float*)d_in[0];  // (8,1,512)
    const float* Wt   = (const float*)d_in[1];  // (10000,1,11)
    const float* Bias = (const float*)d_in[2];  // (10000,)
    // d_in[3] = base (unused: pad recovered from lo/dil/k)
    const int*   dil  = (const int*)d_in[4];
    const int*   lo   = (const int*)d_in[5];
    float* out = (float*)d_out;                 // (8, 20000)

    cudaFuncSetAttribute(rocket_kernel,
                         cudaFuncAttributeMaxDynamicSharedMemorySize, SMEM_BYTES);
    rocket_kernel<<<NBLK, NT, SMEM_BYTES>>>(x, Wt, Bias, dil, lo, out);
}

// round 10
// speedup vs baseline: 1.0860x; 1.0860x over previous
#include <cuda_runtime.h>
#include <math.h>

#define NK     10000
#define SEQ    512
#define XS_POS 1792                      // worst read = 1023 + pad + 4d <= 1618 (M=5, all K)
#define SMEM_BYTES (XS_POS * 8 * 4)      // 57344 B dynamic shared
#define NT     256
#define NBLK   592                       // 4 CTAs/SM * 148 SMs, all resident
#define TOTAL_WARPS (NBLK * (NT / 32))   // 4736

typedef unsigned long long ull;

__device__ int g_ctr;                    // work-steal cursor (self-resetting)
__device__ int g_done;                   // finished-warp count (self-resetting)

static __device__ __forceinline__ ull pack2(float a, float b) {
    ull r; asm("mov.b64 %0, {%1, %2};" : "=l"(r) : "f"(a), "f"(b)); return r;
}
static __device__ __forceinline__ void unpack2(ull v, float& a, float& b) {
    asm("mov.b64 {%0, %1}, %2;" : "=f"(a), "=f"(b) : "l"(v));
}
static __device__ __forceinline__ ull fma2(ull a, ull b, ull c) {
    ull r; asm("fma.rn.f32x2 %0, %1, %2, %3;" : "=l"(r) : "l"(a), "l"(b), "l"(c)); return r;
}

// Process rocket conv-kernel i with compile-time tap count K, tile height M=5.
// Lanes: c = lane>>1 (16 tile-lanes), h = lane&1 (batch half). Tile = M chain-
// consecutive outputs t0..t0+(M-1)d sharing K+M-1 loads. M=5 makes the 8-lane
// phase addresses {2*t0(c)+h} mod 8 all-distinct for every dilation =>
// conflict-free LDS.128 without relying on the swizzle.
// Accumulates s' = -s: max s = -min s'; ppv count = #(s' < 0) via sign bits.
// SAFETY: pad + (M-1)*dil <= 255 + 4*85 = 595 for all K => reads < XS_POS.
template<int K, int M>
static __device__ __forceinline__ void process_i(
    const ulonglong2* __restrict__ xsu, int i, int c, int h,
    const float* __restrict__ w, float bias, int dil, int lo, int pad,
    float* __restrict__ out)
{
    ull wn[K];
#pragma unroll
    for (int j = 0; j < K; ++j) wn[j] = pack2(-w[j], -w[j]);
    const ull biasn = pack2(-bias, -bias);

    const int dM = dil * M;
    const int stripes = (lo + dM - 1) / dM;            // once per item, warp-uniform
    const int ntiles = stripes * dil;
    const float inv_d = 1.0f / (float)dil;
    const int inc = dil * 2;                           // ulonglong2-index step per tap
    const int base0 = (SEQ - pad) * 2 + h;

    float mn0 = INFINITY, mn1 = INFINITY, mn2 = INFINITY, mn3 = INFINITY;
    unsigned cn0 = 0u, cn1 = 0u, cn2 = 0u, cn3 = 0u;

    for (int j = c; j < ntiles; j += 16) {
        // (stripe, off) = (j / dil, j % dil) via float reciprocal + correction
        int stripe = __float2int_rd(__int2float_rn(j) * inv_d);
        int off = j - stripe * dil;
        if (off < 0)         { --stripe; off += dil; }
        else if (off >= dil) { ++stripe; off -= dil; }
        const int t0 = stripe * dM + off;
        if (t0 >= lo) continue;

        int idx = base0 + t0 * 2;
        ull aL[M], aH[M];
#pragma unroll
        for (int q = 0; q < M; ++q) { aL[q] = biasn; aH[q] = biasn; }

#pragma unroll
        for (int v = 0; v < K + M - 1; ++v) {
            const int ph = idx ^ ((idx >> 3) & 6);     // bank swizzle within 128B row
            const ulonglong2 L = xsu[ph];
#pragma unroll
            for (int q = 0; q < M; ++q) {
                const int jj = v - q;
                if (jj >= 0 && jj < K) {
                    aL[q] = fma2(wn[jj], L.x, aL[q]);
                    aH[q] = fma2(wn[jj], L.y, aH[q]);
                }
            }
            idx += inc;
        }

#pragma unroll
        for (int q = 0; q < M; ++q) {
            if (t0 + q * dil < lo) {
                float s0, s1, s2, s3;
                unpack2(aL[q], s0, s1);
                unpack2(aH[q], s2, s3);
                mn0 = fminf(mn0, s0);  cn0 += __float_as_uint(s0) >> 31;
                mn1 = fminf(mn1, s1);  cn1 += __float_as_uint(s1) >> 31;
                mn2 = fminf(mn2, s2);  cn2 += __float_as_uint(s2) >> 31;
                mn3 = fminf(mn3, s3);  cn3 += __float_as_uint(s3) >> 31;
            }
        }
    }

    // reduce across the 16 tile-lanes (xor offsets 2..16 keep h fixed);
    // counts packed 2x16-bit (max 1022 each, no carry)
    unsigned p01 = cn0 | (cn1 << 16);
    unsigned p23 = cn2 | (cn3 << 16);
#pragma unroll
    for (int off = 2; off < 32; off <<= 1) {
        mn0 = fminf(mn0, __shfl_xor_sync(0xffffffffu, mn0, off));
        mn1 = fminf(mn1, __shfl_xor_sync(0xffffffffu, mn1, off));
        mn2 = fminf(mn2, __shfl_xor_sync(0xffffffffu, mn2, off));
        mn3 = fminf(mn3, __shfl_xor_sync(0xffffffffu, mn3, off));
        p01 += __shfl_xor_sync(0xffffffffu, p01, off);
        p23 += __shfl_xor_sync(0xffffffffu, p23, off);
    }

    if (c == 0) {
        const float il = 1.f / (float)lo;
        float2* o2 = reinterpret_cast<float2*>(out);
        o2[(4 * h + 0) * NK + i] = make_float2(-mn0, (float)(p01 & 0xFFFFu) * il);
        o2[(4 * h + 1) * NK + i] = make_float2(-mn1, (float)(p01 >> 16) * il);
        o2[(4 * h + 2) * NK + i] = make_float2(-mn2, (float)(p23 & 0xFFFFu) * il);
        o2[(4 * h + 3) * NK + i] = make_float2(-mn3, (float)(p23 >> 16) * il);
    }
}

__global__ __launch_bounds__(NT, 4)
void rocket_kernel(const float* __restrict__ x,     // (8,1,512)
                   const float* __restrict__ W,     // (10000,1,11)
                   const float* __restrict__ Bias,  // (10000,)
                   const int*   __restrict__ dil_,  // (10000,)
                   const int*   __restrict__ lo_,   // (10000,)
                   float*       __restrict__ out)   // (8, 20000) interleaved (max, ppv)
{
    extern __shared__ float xs[];   // swizzled [pos][8 batches], zero-padded
    const int tid = threadIdx.x;

    // Prologue (single barrier): zero only the two pad regions, transpose x into
    // the middle. Regions disjoint in idx4 space; pad ranges are 128B-row aligned
    // and the swizzle permutes only within rows, so physical zeroing is exact.
    float4* z4 = reinterpret_cast<float4*>(xs);
#pragma unroll
    for (int t = tid; t < 1024; t += NT)
        z4[t] = make_float4(0.f, 0.f, 0.f, 0.f);
#pragma unroll
    for (int t = tid; t < 1536; t += NT)
        z4[2048 + t] = make_float4(0.f, 0.f, 0.f, 0.f);
    for (int t = tid; t < 8 * SEQ; t += NT) {
        int b = t >> 9;
        int s = t & 511;
        int idx4 = (s + SEQ) * 2 + (b >> 2);
        int ph = idx4 ^ ((idx4 >> 3) & 6);
        xs[ph * 4 + (b & 3)] = x[t];
    }
    __syncthreads();

    const int lane = tid & 31;
    const int c = lane >> 1;
    const int h = lane & 1;
    const ulonglong2* xsu = reinterpret_cast<const ulonglong2*>(xs);

    while (true) {
        int i;
        if (lane == 0) i = atomicAdd(&g_ctr, 1);
        i = __shfl_sync(0xffffffffu, i, 0);
        if (i >= NK) break;

        float w[11];
        const float* wr = W + i * 11;
#pragma unroll
        for (int j = 0; j < 11; ++j) w[j] = __ldg(wr + j);
        const float bias = __ldg(Bias + i);
        const int   dil  = __ldg(dil_ + i);
        const int   lo   = __ldg(lo_ + i);

        // recover tap count from exact-zero weight tail; M=5 for all K
        if (w[7] == 0.f && w[8] == 0.f) {
            const int pad = (lo - SEQ + dil * 6) >> 1;
            process_i<7, 5>(xsu, i, c, h, w, bias, dil, lo, pad, out);
        } else if (w[9] == 0.f && w[10] == 0.f) {
            const int pad = (lo - SEQ + dil * 8) >> 1;
            process_i<9, 5>(xsu, i, c, h, w, bias, dil, lo, pad, out);
        } else {
            const int pad = (lo - SEQ + dil * 10) >> 1;
            process_i<11, 5>(xsu, i, c, h, w, bias, dil, lo, pad, out);
        }
    }

    // Self-resetting counters: a warp increments g_done only after its final
    // g_ctr atomic, so the last arrival implies all steals are done. Kernel
    // completion fences the stores for the next graph replay.
    if (lane == 0) {
        int d = atomicAdd(&g_done, 1);
        if (d == TOTAL_WARPS - 1) {
            g_ctr = 0;
            g_done = 0;
        }
    }
}

extern "C" void kernel_launch(void* const* d_in, const int* in_sizes, int n_in,
                              void* d_out, int out_size) {
    const float* x    = (const float*)d_in[0];  // (8,1,512)
    const float* Wt   = (const float*)d_in[1];  // (10000,1,11)
    const float* Bias = (const float*)d_in[2];  // (10000,)
    // d_in[3] = base (unused: pad recovered from lo/dil/k)
    const int*   dil  = (const int*)d_in[4];
    const int*   lo   = (const int*)d_in[5];
    float* out = (float*)d_out;                 // (8, 20000)

    cudaFuncSetAttribute(rocket_kernel,
                         cudaFuncAttributeMaxDynamicSharedMemorySize, SMEM_BYTES);
    rocket_kernel<<<NBLK, NT, SMEM_BYTES>>>(x, Wt, Bias, dil, lo, out);
}

// round 11
// speedup vs baseline: 1.1256x; 1.0365x over previous
#include <cuda_runtime.h>
#include <math.h>

#define NK     10000
#define SEQ    512
#define XS_POS 1792                      // M=5 guarded: worst read 1023+pad+4d <= 1791
#define SMEM_BYTES (XS_POS * 8 * 4)      // 57344 B dynamic shared
#define NT     256
#define NBLK   592                       // 4 CTAs/SM * 148 SMs target
#define TOTAL_WARPS (NBLK * (NT / 32))   // 4736

typedef unsigned long long ull;

__device__ int g_ctr;                    // work-steal cursor (self-resetting)
__device__ int g_done;                   // finished-warp count (self-resetting)

static __device__ __forceinline__ ull pack2(float a, float b) {
    ull r; asm("mov.b64 %0, {%1, %2};" : "=l"(r) : "f"(a), "f"(b)); return r;
}
static __device__ __forceinline__ void unpack2(ull v, float& a, float& b) {
    asm("mov.b64 {%0, %1}, %2;" : "=f"(a), "=f"(b) : "l"(v));
}
static __device__ __forceinline__ ull fma2(ull a, ull b, ull c) {
    ull r; asm("fma.rn.f32x2 %0, %1, %2, %3;" : "=l"(r) : "l"(a), "l"(b), "l"(c)); return r;
}

// Process rocket conv-kernel i with compile-time tap count K, tile height M.
// Lanes: c = lane>>1 (16 tile-lanes), h = lane&1 (batch half). Tile = M chain-
// consecutive outputs t0..t0+(M-1)d sharing K+M-1 loads.
// NO SWIZZLE: for M=5, t0 = j + stripe*4d ≡ j (mod 4) for every d, so each
// quarter-warp's idx values are distinct mod 8 => every LDS.128 is exactly
// 4 conflict-free wavefronts. (M=3 fallback: rare, at worst 2-way.)
// Accumulates s' = -s: max s = -min s'; ppv count = #(s' < 0) via sign bits.
// SAFETY: caller guarantees pad + (M-1)*dil <= 768 so all reads < XS_POS.
template<int K, int M>
static __device__ __forceinline__ void process_i(
    const ulonglong2* __restrict__ xsu, int i, int c, int h,
    const float* __restrict__ w, float bias, int dil, int lo, int pad,
    float* __restrict__ out)
{
    ull wn[K];
#pragma unroll
    for (int j = 0; j < K; ++j) wn[j] = pack2(-w[j], -w[j]);
    const ull biasn = pack2(-bias, -bias);

    const int dM = dil * M;
    const int stripes = (lo + dM - 1) / dM;            // once per item, warp-uniform
    const int ntiles = stripes * dil;
    const float inv_d = 1.0f / (float)dil;
    const int inc = dil * 2;                           // ulonglong2-index step per tap
    const int base0 = (SEQ - pad) * 2 + h;

    float mn0 = INFINITY, mn1 = INFINITY, mn2 = INFINITY, mn3 = INFINITY;
    unsigned cn0 = 0u, cn1 = 0u, cn2 = 0u, cn3 = 0u;

    for (int j = c; j < ntiles; j += 16) {
        // (stripe, off) = (j / dil, j % dil) via float reciprocal + correction
        int stripe = __float2int_rd(__int2float_rn(j) * inv_d);
        int off = j - stripe * dil;
        if (off < 0)         { --stripe; off += dil; }
        else if (off >= dil) { ++stripe; off -= dil; }
        const int t0 = stripe * dM + off;
        if (t0 >= lo) continue;

        int idx = base0 + t0 * 2;
        ull aL[M], aH[M];
#pragma unroll
        for (int q = 0; q < M; ++q) { aL[q] = biasn; aH[q] = biasn; }

#pragma unroll
        for (int v = 0; v < K + M - 1; ++v) {
            const ulonglong2 L = xsu[idx];             // no swizzle: proven conflict-free
#pragma unroll
            for (int q = 0; q < M; ++q) {
                const int jj = v - q;
                if (jj >= 0 && jj < K) {
                    aL[q] = fma2(wn[jj], L.x, aL[q]);
                    aH[q] = fma2(wn[jj], L.y, aH[q]);
                }
            }
            idx += inc;
        }

#pragma unroll
        for (int q = 0; q < M; ++q) {
            if (t0 + q * dil < lo) {
                float s0, s1, s2, s3;
                unpack2(aL[q], s0, s1);
                unpack2(aH[q], s2, s3);
                mn0 = fminf(mn0, s0);  cn0 += __float_as_uint(s0) >> 31;
                mn1 = fminf(mn1, s1);  cn1 += __float_as_uint(s1) >> 31;
                mn2 = fminf(mn2, s2);  cn2 += __float_as_uint(s2) >> 31;
                mn3 = fminf(mn3, s3);  cn3 += __float_as_uint(s3) >> 31;
            }
        }
    }

    // reduce across the 16 tile-lanes (xor offsets 2..16 keep h fixed);
    // counts packed 2x16-bit (max 1022 each, no carry)
    unsigned p01 = cn0 | (cn1 << 16);
    unsigned p23 = cn2 | (cn3 << 16);
#pragma unroll
    for (int off = 2; off < 32; off <<= 1) {
        mn0 = fminf(mn0, __shfl_xor_sync(0xffffffffu, mn0, off));
        mn1 = fminf(mn1, __shfl_xor_sync(0xffffffffu, mn1, off));
        mn2 = fminf(mn2, __shfl_xor_sync(0xffffffffu, mn2, off));
        mn3 = fminf(mn3, __shfl_xor_sync(0xffffffffu, mn3, off));
        p01 += __shfl_xor_sync(0xffffffffu, p01, off);
        p23 += __shfl_xor_sync(0xffffffffu, p23, off);
    }

    if (c == 0) {
        const float il = 1.f / (float)lo;
        float2* o2 = reinterpret_cast<float2*>(out);
        o2[(4 * h + 0) * NK + i] = make_float2(-mn0, (float)(p01 & 0xFFFFu) * il);
        o2[(4 * h + 1) * NK + i] = make_float2(-mn1, (float)(p01 >> 16) * il);
        o2[(4 * h + 2) * NK + i] = make_float2(-mn2, (float)(p23 & 0xFFFFu) * il);
        o2[(4 * h + 3) * NK + i] = make_float2(-mn3, (float)(p23 >> 16) * il);
    }
}

__global__ __launch_bounds__(NT, 4)
void rocket_kernel(const float* __restrict__ x,     // (8,1,512)
                   const float* __restrict__ W,     // (10000,1,11)
                   const float* __restrict__ Bias,  // (10000,)
                   const int*   __restrict__ dil_,  // (10000,)
                   const int*   __restrict__ lo_,   // (10000,)
                   float*       __restrict__ out)   // (8, 20000) interleaved (max, ppv)
{
    extern __shared__ float xs[];   // plain [pos][8 batches] layout, zero-padded
    const int tid = threadIdx.x;

    // Prologue (single barrier): zero the two pad regions, transpose x into the
    // middle. Regions disjoint: pads = float4 idx [0,1024)+[2048,3584), x occupies
    // [1024,2048).
    float4* z4 = reinterpret_cast<float4*>(xs);
#pragma unroll
    for (int t = tid; t < 1024; t += NT)
        z4[t] = make_float4(0.f, 0.f, 0.f, 0.f);
#pragma unroll
    for (int t = tid; t < 1536; t += NT)
        z4[2048 + t] = make_float4(0.f, 0.f, 0.f, 0.f);
    for (int t = tid; t < 8 * SEQ; t += NT) {
        int b = t >> 9;
        int s = t & 511;
        xs[(s + SEQ) * 8 + b] = x[t];
    }
    __syncthreads();

    const int lane = tid & 31;
    const int c = lane >> 1;
    const int h = lane & 1;
    const ulonglong2* xsu = reinterpret_cast<const ulonglong2*>(xs);

    while (true) {
        int i;
        if (lane == 0) i = atomicAdd(&g_ctr, 1);
        i = __shfl_sync(0xffffffffu, i, 0);
        if (i >= NK) break;

        float w[11];
        const float* wr = W + i * 11;
#pragma unroll
        for (int j = 0; j < 11; ++j) w[j] = __ldg(wr + j);
        const float bias = __ldg(Bias + i);
        const int   dil  = __ldg(dil_ + i);
        const int   lo   = __ldg(lo_ + i);

        // recover tap count from exact-zero weight tail; M=5 (guarded), M=3 fallback
        if (w[7] == 0.f && w[8] == 0.f) {
            const int pad = (lo - SEQ + dil * 6) >> 1;
            if (pad + 4 * dil <= 768)
                process_i<7, 5>(xsu, i, c, h, w, bias, dil, lo, pad, out);
            else
                process_i<7, 3>(xsu, i, c, h, w, bias, dil, lo, pad, out);
        } else if (w[9] == 0.f && w[10] == 0.f) {
            const int pad = (lo - SEQ + dil * 8) >> 1;   // pad+4d <= 764 always
            process_i<9, 5>(xsu, i, c, h, w, bias, dil, lo, pad, out);
        } else {
            const int pad = (lo - SEQ + dil * 10) >> 1;  // pad+4d <= 724 always
            process_i<11, 5>(xsu, i, c, h, w, bias, dil, lo, pad, out);
        }
    }

    // Self-resetting counters: a warp increments g_done only after its final
    // g_ctr atomic, so the last arrival implies all steals are done. Kernel
    // completion fences the stores for the next graph replay.
    if (lane == 0) {
        int d = atomicAdd(&g_done, 1);
        if (d == TOTAL_WARPS - 1) {
            g_ctr = 0;
            g_done = 0;
        }
    }
}

extern "C" void kernel_launch(void* const* d_in, const int* in_sizes, int n_in,
                              void* d_out, int out_size) {
    const float* x    = (const float*)d_in[0];  // (8,1,512)
    const float* Wt   = (const float*)d_in[1];  // (10000,1,11)
    const float* Bias = (const float*)d_in[2];  // (10000,)
    // d_in[3] = base (unused: pad recovered from lo/dil/k)
    const int*   dil  = (const int*)d_in[4];
    const int*   lo   = (const int*)d_in[5];
    float* out = (float*)d_out;                 // (8, 20000)

    cudaFuncSetAttribute(rocket_kernel,
                         cudaFuncAttributeMaxDynamicSharedMemorySize, SMEM_BYTES);
    rocket_kernel<<<NBLK, NT, SMEM_BYTES>>>(x, Wt, Bias, dil, lo, out);
}

// round 13
// speedup vs baseline: 1.1276x; 1.0017x over previous
#include <cuda_runtime.h>
#include <math.h>

#define NK     10000
#define SEQ    512
#define XS_POS 1792                      // M=5 guarded: worst read 1023+pad+4d <= 1791
#define SMEM_BYTES (XS_POS * 8 * 4)      // 57344 B dynamic shared
#define NT     256
#define NBLK   592                       // 4 CTAs/SM * 148 SMs target
#define TOTAL_WARPS (NBLK * (NT / 32))   // 4736

typedef unsigned long long ull;

__device__ int g_ctr;                    // work-steal cursor (self-resetting)
__device__ int g_done;                   // finished-warp count (self-resetting)

static __device__ __forceinline__ ull pack2(float a, float b) {
    ull r; asm("mov.b64 %0, {%1, %2};" : "=l"(r) : "f"(a), "f"(b)); return r;
}
static __device__ __forceinline__ ull fma2(ull a, ull b, ull c) {
    ull r; asm("fma.rn.f32x2 %0, %1, %2, %3;" : "=l"(r) : "l"(a), "l"(b), "l"(c)); return r;
}
static __device__ __forceinline__ unsigned lo32(ull v) { return (unsigned)v; }
static __device__ __forceinline__ unsigned hi32(ull v) { return (unsigned)(v >> 32); }

// Process rocket conv-kernel i with compile-time tap count K, tile height M.
// Lanes: c = lane>>1 (16 tile-lanes), h = lane&1 (batch half). Tile = M chain-
// consecutive outputs t0..t0+(M-1)d sharing K+M-1 loads.
// NO SWIZZLE: for M=5, t0 = j + stripe*4d ≡ j (mod 4) for every d, so each
// quarter-warp's idx values are distinct mod 8 => conflict-free LDS.128.
// Accumulates s' = -s: max s = -min s'; ppv counts gathered as sign bytes via
// PRMT into one 4x8-bit counter (per-lane per-batch count <= 64 < 255).
// SAFETY: caller guarantees pad + (M-1)*dil <= 768 so all reads < XS_POS.
template<int K, int M>
static __device__ __forceinline__ void process_i(
    const ulonglong2* __restrict__ xsu, int i, int c, int h,
    const float* __restrict__ w, float bias, int dil, int lo, int pad,
    float* __restrict__ out)
{
    ull wn[K];
#pragma unroll
    for (int j = 0; j < K; ++j) wn[j] = pack2(-w[j], -w[j]);
    const ull biasn = pack2(-bias, -bias);

    const int dM = dil * M;
    const int stripes = (lo + dM - 1) / dM;            // once per item, warp-uniform
    const int ntiles = stripes * dil;
    const float inv_d = 1.0f / (float)dil;
    const int inc = dil * 2;                           // ulonglong2-index step per tap
    const int base0 = (SEQ - pad) * 2 + h;

    float mn0 = INFINITY, mn1 = INFINITY, mn2 = INFINITY, mn3 = INFINITY;
    unsigned c4 = 0u;                                  // 4x8-bit per-batch sign counts

    for (int j = c; j < ntiles; j += 16) {
        // (stripe, off) = (j / dil, j % dil) via float reciprocal + correction
        int stripe = __float2int_rd(__int2float_rn(j) * inv_d);
        int off = j - stripe * dil;
        if (off < 0)         { --stripe; off += dil; }
        else if (off >= dil) { ++stripe; off -= dil; }
        const int t0 = stripe * dM + off;
        if (t0 >= lo) continue;

        int idx = base0 + t0 * 2;
        ull aL[M], aH[M];
#pragma unroll
        for (int q = 0; q < M; ++q) { aL[q] = biasn; aH[q] = biasn; }

#pragma unroll
        for (int v = 0; v < K + M - 1; ++v) {
            const ulonglong2 L = xsu[idx];             // no swizzle: proven conflict-free
#pragma unroll
            for (int q = 0; q < M; ++q) {
                const int jj = v - q;
                if (jj >= 0 && jj < K) {
                    aL[q] = fma2(wn[jj], L.x, aL[q]);
                    aH[q] = fma2(wn[jj], L.y, aH[q]);
                }
            }
            idx += inc;
        }

#pragma unroll
        for (int q = 0; q < M; ++q) {
            if (t0 + q * dil < lo) {
                const unsigned u0 = lo32(aL[q]), u1 = hi32(aL[q]);
                const unsigned u2 = lo32(aH[q]), u3 = hi32(aH[q]);
                mn0 = fminf(mn0, __uint_as_float(u0));
                mn1 = fminf(mn1, __uint_as_float(u1));
                mn2 = fminf(mn2, __uint_as_float(u2));
                mn3 = fminf(mn3, __uint_as_float(u3));
                // gather the 4 sign bytes (byte3 of each f32) into one word
                unsigned t1 = __byte_perm(u0, u1, 0x0073);   // [s0, s1, 0, 0]
                unsigned t2 = __byte_perm(u2, u3, 0x7300);   // [0, 0, s2, s3]
                unsigned tm = __byte_perm(t1, t2, 0x7610);   // [s0, s1, s2, s3]
                c4 += (tm >> 7) & 0x01010101u;
            }
        }
    }

    // reduce across the 16 tile-lanes (xor 2..16 keeps h fixed);
    // counts unpacked to 2x16-bit (sums <= 1022, no carry)
    unsigned p01 = __byte_perm(c4, 0u, 0x4140);        // cnt0 | cnt1<<16
    unsigned p23 = __byte_perm(c4, 0u, 0x4342);        // cnt2 | cnt3<<16
#pragma unroll
    for (int off = 2; off < 32; off <<= 1) {
        mn0 = fminf(mn0, __shfl_xor_sync(0xffffffffu, mn0, off));
        mn1 = fminf(mn1, __shfl_xor_sync(0xffffffffu, mn1, off));
        mn2 = fminf(mn2, __shfl_xor_sync(0xffffffffu, mn2, off));
        mn3 = fminf(mn3, __shfl_xor_sync(0xffffffffu, mn3, off));
        p01 += __shfl_xor_sync(0xffffffffu, p01, off);
        p23 += __shfl_xor_sync(0xffffffffu, p23, off);
    }

    if (c == 0) {
        const float il = 1.f / (float)lo;
        float2* o2 = reinterpret_cast<float2*>(out);
        o2[(4 * h + 0) * NK + i] = make_float2(-mn0, (float)(p01 & 0xFFFFu) * il);
        o2[(4 * h + 1) * NK + i] = make_float2(-mn1, (float)(p01 >> 16) * il);
        o2[(4 * h + 2) * NK + i] = make_float2(-mn2, (float)(p23 & 0xFFFFu) * il);
        o2[(4 * h + 3) * NK + i] = make_float2(-mn3, (float)(p23 >> 16) * il);
    }
}

__global__ __launch_bounds__(NT, 4)
void rocket_kernel(const float* __restrict__ x,     // (8,1,512)
                   const float* __restrict__ W,     // (10000,1,11)
                   const float* __restrict__ Bias,  // (10000,)
                   const int*   __restrict__ dil_,  // (10000,)
                   const int*   __restrict__ lo_,   // (10000,)
                   float*       __restrict__ out)   // (8, 20000) interleaved (max, ppv)
{
    extern __shared__ float xs[];   // plain [pos][8 batches] layout, zero-padded
    const int tid = threadIdx.x;

    // Prologue (single barrier): zero the two pad regions, transpose x into the
    // middle. Regions disjoint: pads = float4 idx [0,1024)+[2048,3584), x occupies
    // [1024,2048).
    float4* z4 = reinterpret_cast<float4*>(xs);
#pragma unroll
    for (int t = tid; t < 1024; t += NT)
        z4[t] = make_float4(0.f, 0.f, 0.f, 0.f);
#pragma unroll
    for (int t = tid; t < 1536; t += NT)
        z4[2048 + t] = make_float4(0.f, 0.f, 0.f, 0.f);
    for (int t = tid; t < 8 * SEQ; t += NT) {
        int b = t >> 9;
        int s = t & 511;
        xs[(s + SEQ) * 8 + b] = x[t];
    }
    __syncthreads();

    const int lane = tid & 31;
    const int c = lane >> 1;
    const int h = lane & 1;
    const ulonglong2* xsu = reinterpret_cast<const ulonglong2*>(xs);

    while (true) {
        int i;
        if (lane == 0) i = atomicAdd(&g_ctr, 1);
        i = __shfl_sync(0xffffffffu, i, 0);
        if (i >= NK) break;

        float w[11];
        const float* wr = W + i * 11;
#pragma unroll
        for (int j = 0; j < 11; ++j) w[j] = __ldg(wr + j);
        const float bias = __ldg(Bias + i);
        const int   dil  = __ldg(dil_ + i);
        const int   lo   = __ldg(lo_ + i);

        // recover tap count from exact-zero weight tail; M=5 (guarded), M=3 fallback
        if (w[7] == 0.f && w[8] == 0.f) {
            const int pad = (lo - SEQ + dil * 6) >> 1;
            if (pad + 4 * dil <= 768)
                process_i<7, 5>(xsu, i, c, h, w, bias, dil, lo, pad, out);
            else
                process_i<7, 3>(xsu, i, c, h, w, bias, dil, lo, pad, out);
        } else if (w[9] == 0.f && w[10] == 0.f) {
            const int pad = (lo - SEQ + dil * 8) >> 1;   // pad+4d <= 764 always
            process_i<9, 5>(xsu, i, c, h, w, bias, dil, lo, pad, out);
        } else {
            const int pad = (lo - SEQ + dil * 10) >> 1;  // pad+4d <= 724 always
            process_i<11, 5>(xsu, i, c, h, w, bias, dil, lo, pad, out);
        }
    }

    // Self-resetting counters: a warp increments g_done only after its final
    // g_ctr atomic, so the last arrival implies all steals are done. Kernel
    // completion fences the stores for the next graph replay.
    if (lane == 0) {
        int d = atomicAdd(&g_done, 1);
        if (d == TOTAL_WARPS - 1) {
            g_ctr = 0;
            g_done = 0;
        }
    }
}

extern "C" void kernel_launch(void* const* d_in, const int* in_sizes, int n_in,
                              void* d_out, int out_size) {
    const float* x    = (const float*)d_in[0];  // (8,1,512)
    const float* Wt   = (const float*)d_in[1];  // (10000,1,11)
    const float* Bias = (const float*)d_in[2];  // (10000,)
    // d_in[3] = base (unused: pad recovered from lo/dil/k)
    const int*   dil  = (const int*)d_in[4];
    const int*   lo   = (const int*)d_in[5];
    float* out = (float*)d_out;                 // (8, 20000)

    cudaFuncSetAttribute(rocket_kernel,
                         cudaFuncAttributeMaxDynamicSharedMemorySize, SMEM_BYTES);
    rocket_kernel<<<NBLK, NT, SMEM_BYTES>>>(x, Wt, Bias, dil, lo, out);
}